// round 16
// baseline (speedup 1.0000x reference)
#include <cuda_runtime.h>
#include <math.h>

#define SEQ 640
#define BATCH 40
#define DIN 8
#define DL 64
#define NH 4
#define DH 48
#define EMB 192
#define ROWS (SEQ*BATCH)   // 25600

typedef unsigned long long ull;

// ---------------- scratch ----------------
__device__ float d_gx[ROWS * 256];
__device__ float d_seq[ROWS * DL];
__device__ float d_q[ROWS * EMB];
__device__ float d_k[ROWS * EMB];
__device__ float d_v[ROWS * EMB];
__device__ float d_att[ROWS * EMB];

__device__ __forceinline__ float sigf(float x) { return 1.f / (1.f + __expf(-x)); }

__device__ __forceinline__ float tanh_mufu(float x) {
    float y;
    asm("tanh.approx.f32 %0, %1;" : "=f"(y) : "f"(x));
    return y;
}

__device__ __forceinline__ ull fma2(ull a, ull b, ull c) {
    ull d;
    asm("fma.rn.f32x2 %0, %1, %2, %3;" : "=l"(d) : "l"(a), "l"(b), "l"(c));
    return d;
}
__device__ __forceinline__ float lo32(ull u) { return __uint_as_float((unsigned)u); }
__device__ __forceinline__ float hi32(ull u) { return __uint_as_float((unsigned)(u >> 32)); }
__device__ __forceinline__ float sum2(ull u) { return lo32(u) + hi32(u); }

// ---- tf32 mma helpers ----
__device__ __forceinline__ unsigned cvt_tf32(float x) {
    unsigned r;
    asm("cvt.rna.tf32.f32 %0, %1;" : "=r"(r) : "f"(x));
    return r;
}
__device__ __forceinline__ void mma_tf32(
    float& c0, float& c1, float& c2, float& c3,
    unsigned a0, unsigned a1, unsigned a2, unsigned a3,
    unsigned b0, unsigned b1)
{
    asm("mma.sync.aligned.m16n8k8.row.col.f32.tf32.tf32.f32 "
        "{%0,%1,%2,%3},{%4,%5,%6,%7},{%8,%9},{%0,%1,%2,%3};"
        : "+f"(c0), "+f"(c1), "+f"(c2), "+f"(c3)
        : "r"(a0), "r"(a1), "r"(a2), "r"(a3), "r"(b0), "r"(b1));
}

// ---------------- dummy no-op kernels (keep k2 in ncu's captured slot) ----------------
__device__ int d_dummy_sink;
__global__ void k_dummy1() { if (threadIdx.x == 1024) d_dummy_sink = 1; }
__global__ void k_dummy2() { if (threadIdx.x == 1024) d_dummy_sink = 2; }

// ---------------- K1: embed + gates_x ----------------
__global__ void __launch_bounds__(256) k1_embed_gates(
    const float* __restrict__ hist, const float* __restrict__ W1,
    const float* __restrict__ b1, const float* __restrict__ W_ih,
    const float* __restrict__ b_ih, const float* __restrict__ b_hh)
{
    __shared__ __align__(16) float xs[8 * 32];
    int tid = threadIdx.x;

    ull w2[16];
    const ull* wp = (const ull*)(W_ih + tid * 32);
#pragma unroll
    for (int i = 0; i < 16; i++) w2[i] = wp[i];
    float bsum = b_ih[tid] + b_hh[tid];

    int rl = tid >> 5, j = tid & 31;
    const float* hp = hist + (blockIdx.x * 8 + rl) * DIN;
    float acc = b1[j];
#pragma unroll
    for (int f = 0; f < DIN; f++) acc = fmaf(hp[f], W1[j * DIN + f], acc);
    xs[rl * 32 + j] = acc > 0.f ? acc : expm1f(acc);
    __syncthreads();

#pragma unroll
    for (int r = 0; r < 8; r++) {
        const ulonglong2* xv = (const ulonglong2*)(xs + r * 32);
        ull s0 = 0, s1 = 0;
#pragma unroll
        for (int q = 0; q < 8; q++) {
            ulonglong2 x2 = xv[q];
            s0 = fma2(x2.x, w2[2 * q], s0);
            s1 = fma2(x2.y, w2[2 * q + 1], s1);
        }
        d_gx[(blockIdx.x * 8 + r) * 256 + tid] = bsum + (sum2(s0) + sum2(s1));
    }
}

// ---------------- K2: LSTM, TWO batch lanes per block, per-lane named barriers ----------------
// 512 threads: tid<256 -> lane A (warps 0-7), tid>=256 -> lane B (warps 8-15).
// Each lane = R14-proven structure: warp w owns j in [8w,8w+8), lane = g*8+jj,
// branchless MUFU act, xor8/16/24 gate exchange, ping-pong h, ONE named barrier/step.
// Independent chains interleave on the SM pipes -> latency hiding without stragglers.
__global__ void __launch_bounds__(512) k2_lstm(const float* __restrict__ W_hh)
{
    __shared__ __align__(16) float h_buf[2][2][64];   // [lane][phase][j]
    int tid = threadIdx.x;
    int li = tid >> 8;                 // lane-in-block: 0 or 1
    int t = tid & 255;
    int b = blockIdx.x * 2 + li;
    int lane = t & 31, w = t >> 5;
    int g = lane >> 3, jj = lane & 7;
    int j = w * 8 + jj;
    int r = g * 64 + j;
    int barid = li + 1;

    ull w2[32];
    const ull* wp = (const ull*)(W_hh + r * 64);
#pragma unroll
    for (int i = 0; i < 32; i++) w2[i] = wp[i];

    float s_in  = (g == 2) ? 1.f : 0.5f;
    float s_add = (g == 2) ? 0.f : 0.5f;

    float c = 0.f;
    if (t < 64) h_buf[li][0][t] = 0.f;

    const float* gxp = d_gx + b * 256 + r;
    float* seqp = d_seq + b * 64 + j;
    float gx_c = gxp[0]; gxp += BATCH * 256;
    float gx_n = gxp[0]; gxp += BATCH * 256;
    asm volatile("bar.sync %0, %1;" :: "r"(barid), "r"(256) : "memory");

    int p = 0;
    for (int step = 0; step < SEQ; step++) {
        float gx_f = (step + 2 < SEQ) ? gxp[0] : 0.f;
        gxp += BATCH * 256;

        const ulonglong2* h2 = (const ulonglong2*)h_buf[li][p];
        ull a0 = 0, a1 = 0, a2 = 0, a3 = 0;
#pragma unroll
        for (int i = 0; i < 8; i++) {
            ulonglong2 hp_ = h2[2 * i], hq_ = h2[2 * i + 1];
            a0 = fma2(hp_.x, w2[4 * i + 0], a0);
            a1 = fma2(hp_.y, w2[4 * i + 1], a1);
            a2 = fma2(hq_.x, w2[4 * i + 2], a2);
            a3 = fma2(hq_.y, w2[4 * i + 3], a3);
        }
        float gate = gx_c + ((sum2(a0) + sum2(a1)) + (sum2(a2) + sum2(a3)));
        float act = fmaf(tanh_mufu(gate * s_in), s_in, s_add);

        float tg16 = __shfl_xor_sync(0xFFFFFFFFu, act, 16);  // g0 gets tanh(g)
        float fv   = __shfl_xor_sync(0xFFFFFFFFu, act, 8);   // g0 gets sig(f)
        float ov   = __shfl_xor_sync(0xFFFFFFFFu, act, 24);  // g0 gets sig(o)

        if (g == 0) {
            c = fv * c + act * tg16;
            float hv = ov * tanh_mufu(c);
            h_buf[li][1 - p][j] = hv;
            seqp[0] = hv;
        }
        asm volatile("bar.sync %0, %1;" :: "r"(barid), "r"(256) : "memory");
        p ^= 1;
        seqp += BATCH * 64;
        gx_c = gx_n; gx_n = gx_f;
    }
}

// ---------------- K3: QKV GEMM via tf32 mma.sync (proven R11 version) ----------------
__global__ void __launch_bounds__(256) k3_qkv(
    const float* __restrict__ Wq, const float* __restrict__ bq,
    const float* __restrict__ Wk, const float* __restrict__ bk,
    const float* __restrict__ Wv, const float* __restrict__ bv)
{
    __shared__ unsigned As[64 * 68];
    __shared__ unsigned Bs[64 * 68];
    int tid = threadIdx.x;
    int mt = blockIdx.x, nt = blockIdx.y;

    const float* W; const float* bias; float* out; int n0;
    if (nt < 3)      { W = Wq; bias = bq; out = d_q; n0 = nt * 64; }
    else if (nt < 6) { W = Wk; bias = bk; out = d_k; n0 = (nt - 3) * 64; }
    else             { W = Wv; bias = bv; out = d_v; n0 = (nt - 6) * 64; }

#pragma unroll
    for (int s = 0; s < 4; s++) {
        int e = tid + s * 256;
        int r = e >> 4, c4 = e & 15;
        float4 v = *(const float4*)&d_seq[(mt * 64 + r) * 64 + c4 * 4];
        uint4 u = make_uint4(cvt_tf32(v.x), cvt_tf32(v.y), cvt_tf32(v.z), cvt_tf32(v.w));
        *(uint4*)&As[r * 68 + c4 * 4] = u;
    }
#pragma unroll
    for (int s = 0; s < 4; s++) {
        int e = tid + s * 256;
        int r = e >> 4, c4 = e & 15;
        float4 v = *(const float4*)&W[(n0 + r) * 64 + c4 * 4];
        uint4 u = make_uint4(cvt_tf32(v.x), cvt_tf32(v.y), cvt_tf32(v.z), cvt_tf32(v.w));
        *(uint4*)&Bs[r * 68 + c4 * 4] = u;
    }
    __syncthreads();

    int lane = tid & 31, wid = tid >> 5;
    int wm = wid >> 1, wn = wid & 1;
    int g = lane >> 2, tg = lane & 3;

    float acc[4][4] = {};
    int ar0 = (wm * 16 + g) * 68;
    int ar1 = ar0 + 8 * 68;
#pragma unroll
    for (int k8 = 0; k8 < 8; k8++) {
        int kb = k8 * 8 + tg;
        unsigned a0 = As[ar0 + kb];
        unsigned a1 = As[ar1 + kb];
        unsigned a2 = As[ar0 + kb + 4];
        unsigned a3 = As[ar1 + kb + 4];
#pragma unroll
        for (int ntl = 0; ntl < 4; ntl++) {
            int bb = (wn * 32 + ntl * 8 + g) * 68 + kb;
            unsigned b0 = Bs[bb];
            unsigned b1 = Bs[bb + 4];
            mma_tf32(acc[ntl][0], acc[ntl][1], acc[ntl][2], acc[ntl][3],
                     a0, a1, a2, a3, b0, b1);
        }
    }

#pragma unroll
    for (int ntl = 0; ntl < 4; ntl++) {
        int col = n0 + wn * 32 + ntl * 8 + 2 * tg;
        float2 b2 = *(const float2*)&bias[col];
        int row0 = mt * 64 + wm * 16 + g;
        float2 o0 = make_float2(acc[ntl][0] + b2.x, acc[ntl][1] + b2.y);
        float2 o1 = make_float2(acc[ntl][2] + b2.x, acc[ntl][3] + b2.y);
        *(float2*)&out[row0 * EMB + col] = o0;
        *(float2*)&out[(row0 + 8) * EMB + col] = o1;
    }
}

// ---------------- K4: attention via tf32 mma.sync (proven R11 version) ----------------
__global__ void __launch_bounds__(128) k4_attn()
{
    __shared__ __align__(16) unsigned qt[40 * 52];
    __shared__ __align__(16) unsigned kt[40 * 52];
    __shared__ __align__(16) unsigned vt[40 * 52];
    __shared__ __align__(16) float ss[40 * 44];
    int t = blockIdx.x, h = blockIdx.y;
    int tid = threadIdx.x;

#pragma unroll
    for (int ii = 0; ii < 12; ii++) {
        int e = tid + ii * 128;
        if (e < 1440) {
            int arr = e / 480, idx = e - arr * 480;
            int r = idx / 12, c4 = idx - r * 12;
            const float* src = arr == 0 ? d_q : (arr == 1 ? d_k : d_v);
            unsigned* dst = arr == 0 ? qt : (arr == 1 ? kt : vt);
            float4 v = *(const float4*)&src[(t * BATCH + r) * EMB + h * DH + c4 * 4];
            uint4 u = make_uint4(cvt_tf32(v.x), cvt_tf32(v.y), cvt_tf32(v.z), cvt_tf32(v.w));
            *(uint4*)&dst[r * 52 + c4 * 4] = u;
        }
    }
    __syncthreads();

    int lane = tid & 31, wid = tid >> 5;
    int g = lane >> 2, tg = lane & 3;

    if (wid < 3) {
        int m0 = wid * 16;
        int r0 = min(m0 + g, 39), r1 = min(m0 + g + 8, 39);
        float acc[5][4] = {};
#pragma unroll
        for (int k8 = 0; k8 < 6; k8++) {
            int kb = k8 * 8 + tg;
            unsigned a0 = qt[r0 * 52 + kb];
            unsigned a1 = qt[r1 * 52 + kb];
            unsigned a2 = qt[r0 * 52 + kb + 4];
            unsigned a3 = qt[r1 * 52 + kb + 4];
#pragma unroll
            for (int ntl = 0; ntl < 5; ntl++) {
                unsigned b0 = kt[(ntl * 8 + g) * 52 + kb];
                unsigned b1 = kt[(ntl * 8 + g) * 52 + kb + 4];
                mma_tf32(acc[ntl][0], acc[ntl][1], acc[ntl][2], acc[ntl][3],
                         a0, a1, a2, a3, b0, b1);
            }
        }
        int row0 = m0 + g, row1 = m0 + g + 8;
#pragma unroll
        for (int ntl = 0; ntl < 5; ntl++) {
            int col = ntl * 8 + 2 * tg;
            if (row0 < 40) {
                ss[row0 * 44 + col] = acc[ntl][0] * 0.125f;
                ss[row0 * 44 + col + 1] = acc[ntl][1] * 0.125f;
            }
            if (row1 < 40) {
                ss[row1 * 44 + col] = acc[ntl][2] * 0.125f;
                ss[row1 * 44 + col + 1] = acc[ntl][3] * 0.125f;
            }
        }
    }
    __syncthreads();

    if (tid < 40) {
        float m = -1e30f;
#pragma unroll
        for (int j = 0; j < 40; j++) m = fmaxf(m, ss[tid * 44 + j]);
        float p[40]; float sum = 0.f;
#pragma unroll
        for (int j = 0; j < 40; j++) { p[j] = __expf(ss[tid * 44 + j] - m); sum += p[j]; }
        float inv = 1.f / sum;
        unsigned* pr = (unsigned*)ss + tid * 44;
#pragma unroll
        for (int j = 0; j < 40; j++) pr[j] = cvt_tf32(p[j] * inv);
    }
    __syncthreads();

    const unsigned* pt = (const unsigned*)ss;
    for (int idx = wid; idx < 18; idx += 4) {
        int mtile = idx / 6, ntile = idx - mtile * 6;
        int m0 = mtile * 16, n0 = ntile * 8;
        int r0 = min(m0 + g, 39), r1 = min(m0 + g + 8, 39);
        float acc0 = 0.f, acc1 = 0.f, acc2 = 0.f, acc3 = 0.f;
#pragma unroll
        for (int k8 = 0; k8 < 5; k8++) {
            int kb = k8 * 8 + tg;
            mma_tf32(acc0, acc1, acc2, acc3,
                     pt[r0 * 44 + kb], pt[r1 * 44 + kb],
                     pt[r0 * 44 + kb + 4], pt[r1 * 44 + kb + 4],
                     vt[kb * 52 + n0 + g], vt[(kb + 4) * 52 + n0 + g]);
        }
        int col = n0 + 2 * tg;
        int row0 = m0 + g, row1 = m0 + g + 8;
        if (row0 < 40)
            *(float2*)&d_att[(t * BATCH + row0) * EMB + h * DH + col] = make_float2(acc0, acc1);
        if (row1 < 40)
            *(float2*)&d_att[(t * BATCH + row1) * EMB + h * DH + col] = make_float2(acc2, acc3);
    }
}

// ---------------- K5: tf32 mma GLU GEMM + GLU + residual + LN (proven R11) ----------------
__global__ void __launch_bounds__(256) k5_glu_ln(
    const float* __restrict__ Wa, const float* __restrict__ ba,
    const float* __restrict__ Wg, const float* __restrict__ bg,
    const float* __restrict__ gamma, const float* __restrict__ beta,
    float* __restrict__ out)
{
    __shared__ __align__(16) float buf[64 * 136];
    unsigned* As = (unsigned*)buf;
    unsigned* Bs = (unsigned*)buf + 64 * 36;
    float* os = buf;
    int tid = threadIdx.x;
    int mt = blockIdx.x;

    int lane = tid & 31, wid = tid >> 5;
    int wm = wid >> 2, wn = wid & 3;
    int g = lane >> 2, tg = lane & 3;

    float acc[2][4][4] = {};

    for (int kc = 0; kc < 6; kc++) {
#pragma unroll
        for (int s = 0; s < 2; s++) {
            int e = tid + s * 256;
            int r = e >> 3, c4 = e & 7;
            float4 v = *(const float4*)&d_att[(mt * 64 + r) * EMB + kc * 32 + c4 * 4];
            uint4 u = make_uint4(cvt_tf32(v.x), cvt_tf32(v.y), cvt_tf32(v.z), cvt_tf32(v.w));
            *(uint4*)&As[r * 36 + c4 * 4] = u;
        }
#pragma unroll
        for (int s = 0; s < 4; s++) {
            int e = tid + s * 256;
            int r = e >> 3, c4 = e & 7;
            const float* Wsrc = (r < 64) ? &Wa[r * EMB] : &Wg[(r - 64) * EMB];
            float4 v = *(const float4*)&Wsrc[kc * 32 + c4 * 4];
            uint4 u = make_uint4(cvt_tf32(v.x), cvt_tf32(v.y), cvt_tf32(v.z), cvt_tf32(v.w));
            *(uint4*)&Bs[r * 36 + c4 * 4] = u;
        }
        __syncthreads();

#pragma unroll
        for (int k8 = 0; k8 < 4; k8++) {
            int kb = k8 * 8 + tg;
            unsigned a[2][4];
#pragma unroll
            for (int mtl = 0; mtl < 2; mtl++) {
                int ar0 = (wm * 32 + mtl * 16 + g) * 36;
                a[mtl][0] = As[ar0 + kb];
                a[mtl][1] = As[ar0 + 8 * 36 + kb];
                a[mtl][2] = As[ar0 + kb + 4];
                a[mtl][3] = As[ar0 + 8 * 36 + kb + 4];
            }
#pragma unroll
            for (int ntl = 0; ntl < 4; ntl++) {
                int bb = (wn * 32 + ntl * 8 + g) * 36 + kb;
                unsigned b0 = Bs[bb];
                unsigned b1 = Bs[bb + 4];
#pragma unroll
                for (int mtl = 0; mtl < 2; mtl++)
                    mma_tf32(acc[mtl][ntl][0], acc[mtl][ntl][1],
                             acc[mtl][ntl][2], acc[mtl][ntl][3],
                             a[mtl][0], a[mtl][1], a[mtl][2], a[mtl][3], b0, b1);
            }
        }
        __syncthreads();
    }

#pragma unroll
    for (int mtl = 0; mtl < 2; mtl++) {
#pragma unroll
        for (int ntl = 0; ntl < 4; ntl++) {
            int col = wn * 32 + ntl * 8 + 2 * tg;
            float2 b2 = (col < 64) ? *(const float2*)&ba[col]
                                   : *(const float2*)&bg[col - 64];
            int row0 = wm * 32 + mtl * 16 + g;
            os[row0 * 136 + col]     = acc[mtl][ntl][0] + b2.x;
            os[row0 * 136 + col + 1] = acc[mtl][ntl][1] + b2.y;
            os[(row0 + 8) * 136 + col]     = acc[mtl][ntl][2] + b2.x;
            os[(row0 + 8) * 136 + col + 1] = acc[mtl][ntl][3] + b2.y;
        }
    }
    __syncthreads();

    {
        int r = tid >> 2, q = tid & 3;
        int c0 = q * 16;
        int grow = mt * 64 + r;
        float y[16];
        float s = 0.f, s2 = 0.f;
#pragma unroll
        for (int c = 0; c < 16; c++) {
            int j = c0 + c;
            float a = os[r * 136 + j];
            float g2 = os[r * 136 + 64 + j];
            float yv = d_seq[grow * 64 + j] + a * sigf(g2);
            y[c] = yv; s += yv; s2 += yv * yv;
        }
        s += __shfl_xor_sync(0xFFFFFFFFu, s, 1);
        s += __shfl_xor_sync(0xFFFFFFFFu, s, 2);
        s2 += __shfl_xor_sync(0xFFFFFFFFu, s2, 1);
        s2 += __shfl_xor_sync(0xFFFFFFFFu, s2, 2);
        float mu = s * (1.f / 64.f);
        float var = s2 * (1.f / 64.f) - mu * mu;
        float inv = rsqrtf(var + 1e-5f);
#pragma unroll
        for (int c = 0; c < 16; c++) {
            int j = c0 + c;
            out[grow * 64 + j] = (y[c] - mu) * inv * gamma[j] + beta[j];
        }
    }
}

// ---------------- launch ----------------
extern "C" void kernel_launch(void* const* d_in, const int* in_sizes, int n_in,
                              void* d_out, int out_size)
{
    const float* hist = (const float*)d_in[0];
    const float* W1   = (const float*)d_in[2];
    const float* b1   = (const float*)d_in[3];
    const float* W_ih = (const float*)d_in[4];
    const float* W_hh = (const float*)d_in[5];
    const float* b_ih = (const float*)d_in[6];
    const float* b_hh = (const float*)d_in[7];
    const float* Wq   = (const float*)d_in[8];
    const float* bq   = (const float*)d_in[9];
    const float* Wk   = (const float*)d_in[10];
    const float* bk   = (const float*)d_in[11];
    const float* Wv   = (const float*)d_in[12];
    const float* bv   = (const float*)d_in[13];
    const float* Wa   = (const float*)d_in[14];
    const float* ba   = (const float*)d_in[15];
    const float* Wg   = (const float*)d_in[16];
    const float* bg   = (const float*)d_in[17];
    const float* gamma= (const float*)d_in[18];
    const float* beta = (const float*)d_in[19];
    float* out = (float*)d_out;

    k1_embed_gates<<<ROWS / 8, 256>>>(hist, W1, b1, W_ih, b_ih, b_hh);
    k_dummy1<<<1, 32>>>();               // keep k2 in ncu capture slot (abs launch #4)
    k_dummy2<<<1, 32>>>();
    k2_lstm<<<BATCH / 2, 512>>>(W_hh);   // 2 lanes per block, per-lane named barriers
    k3_qkv<<<dim3(ROWS / 64, 9), 256>>>(Wq, bq, Wk, bk, Wv, bv);
    k4_attn<<<dim3(SEQ, NH), 128>>>();
    k5_glu_ln<<<ROWS / 64, 256>>>(Wa, ba, Wg, bg, gamma, beta, out);
}

// round 17
// speedup vs baseline: 1.3775x; 1.3775x over previous
#include <cuda_runtime.h>
#include <math.h>

#define SEQ 640
#define BATCH 40
#define DIN 8
#define DL 64
#define NH 4
#define DH 48
#define EMB 192
#define ROWS (SEQ*BATCH)   // 25600

typedef unsigned long long ull;

// ---------------- scratch ----------------
__device__ float d_gx[ROWS * 256];
__device__ float d_seq[ROWS * DL];
__device__ float d_q[ROWS * EMB];
__device__ float d_k[ROWS * EMB];
__device__ float d_v[ROWS * EMB];
__device__ float d_att[ROWS * EMB];

__device__ __forceinline__ float sigf(float x) { return 1.f / (1.f + __expf(-x)); }

__device__ __forceinline__ float tanh_mufu(float x) {
    float y;
    asm("tanh.approx.f32 %0, %1;" : "=f"(y) : "f"(x));
    return y;
}

__device__ __forceinline__ ull fma2(ull a, ull b, ull c) {
    ull d;
    asm("fma.rn.f32x2 %0, %1, %2, %3;" : "=l"(d) : "l"(a), "l"(b), "l"(c));
    return d;
}
__device__ __forceinline__ float lo32(ull u) { return __uint_as_float((unsigned)u); }
__device__ __forceinline__ float hi32(ull u) { return __uint_as_float((unsigned)(u >> 32)); }
__device__ __forceinline__ float sum2(ull u) { return lo32(u) + hi32(u); }

// ---- tf32 mma helpers ----
__device__ __forceinline__ unsigned cvt_tf32(float x) {
    unsigned r;
    asm("cvt.rna.tf32.f32 %0, %1;" : "=r"(r) : "f"(x));
    return r;
}
__device__ __forceinline__ void mma_tf32(
    float& c0, float& c1, float& c2, float& c3,
    unsigned a0, unsigned a1, unsigned a2, unsigned a3,
    unsigned b0, unsigned b1)
{
    asm("mma.sync.aligned.m16n8k8.row.col.f32.tf32.tf32.f32 "
        "{%0,%1,%2,%3},{%4,%5,%6,%7},{%8,%9},{%0,%1,%2,%3};"
        : "+f"(c0), "+f"(c1), "+f"(c2), "+f"(c3)
        : "r"(a0), "r"(a1), "r"(a2), "r"(a3), "r"(b0), "r"(b1));
}

// ---------------- K1: embed + gates_x (stores gx PERMUTED for coalesced k2 reads) ----------------
// k2 thread (w, lane=g*8+jj) handles gate-row r = g*64+8w+jj and reads slot w*32+lane.
// So k1 (computing row r = tid) stores at p(r) = ((r>>3)&7)*32 + (r>>6)*8 + (r&7).
__global__ void __launch_bounds__(256) k1_embed_gates(
    const float* __restrict__ hist, const float* __restrict__ W1,
    const float* __restrict__ b1, const float* __restrict__ W_ih,
    const float* __restrict__ b_ih, const float* __restrict__ b_hh)
{
    __shared__ __align__(16) float xs[8 * 32];
    int tid = threadIdx.x;

    ull w2[16];
    const ull* wp = (const ull*)(W_ih + tid * 32);
#pragma unroll
    for (int i = 0; i < 16; i++) w2[i] = wp[i];
    float bsum = b_ih[tid] + b_hh[tid];

    int rl = tid >> 5, j = tid & 31;
    const float* hp = hist + (blockIdx.x * 8 + rl) * DIN;
    float acc = b1[j];
#pragma unroll
    for (int f = 0; f < DIN; f++) acc = fmaf(hp[f], W1[j * DIN + f], acc);
    xs[rl * 32 + j] = acc > 0.f ? acc : expm1f(acc);
    __syncthreads();

    int p = ((tid >> 3) & 7) * 32 + (tid >> 6) * 8 + (tid & 7);  // permuted slot

#pragma unroll
    for (int r = 0; r < 8; r++) {
        const ulonglong2* xv = (const ulonglong2*)(xs + r * 32);
        ull s0 = 0, s1 = 0;
#pragma unroll
        for (int q = 0; q < 8; q++) {
            ulonglong2 x2 = xv[q];
            s0 = fma2(x2.x, w2[2 * q], s0);
            s1 = fma2(x2.y, w2[2 * q + 1], s1);
        }
        d_gx[(blockIdx.x * 8 + r) * 256 + p] = bsum + (sum2(s0) + sum2(s1));
    }
}

// ---------------- K2: LSTM (R11 best; gx reads now fully coalesced: slot = tid) ----------------
__global__ void __launch_bounds__(256) k2_lstm(const float* __restrict__ W_hh)
{
    __shared__ __align__(16) float h_buf[2][64];
    int tid = threadIdx.x;
    int b = blockIdx.x;
    int lane = tid & 31, w = tid >> 5;
    int g = lane >> 3, jj = lane & 7;
    int j = w * 8 + jj;
    int r = g * 64 + j;

    ull w2[32];
    const ull* wp = (const ull*)(W_hh + r * 64);
#pragma unroll
    for (int i = 0; i < 32; i++) w2[i] = wp[i];

    float s_in  = (g == 2) ? 1.f : 0.5f;
    float s_add = (g == 2) ? 0.f : 0.5f;

    float c = 0.f;
    if (tid < 64) h_buf[0][tid] = 0.f;

    const float* gxp = d_gx + b * 256 + tid;   // permuted layout: warp reads 1 contiguous 128B line
    float* seqp = d_seq + b * 64 + j;
    float gx_c = gxp[0]; gxp += BATCH * 256;
    float gx_n = gxp[0]; gxp += BATCH * 256;
    __syncthreads();

    int p = 0;
    for (int step = 0; step < SEQ; step++) {
        float gx_f = (step + 2 < SEQ) ? gxp[0] : 0.f;
        gxp += BATCH * 256;

        const ulonglong2* h2 = (const ulonglong2*)h_buf[p];
        ull a0 = 0, a1 = 0, a2 = 0, a3 = 0;
#pragma unroll
        for (int i = 0; i < 8; i++) {
            ulonglong2 hp_ = h2[2 * i], hq_ = h2[2 * i + 1];
            a0 = fma2(hp_.x, w2[4 * i + 0], a0);
            a1 = fma2(hp_.y, w2[4 * i + 1], a1);
            a2 = fma2(hq_.x, w2[4 * i + 2], a2);
            a3 = fma2(hq_.y, w2[4 * i + 3], a3);
        }
        float gate = gx_c + ((sum2(a0) + sum2(a1)) + (sum2(a2) + sum2(a3)));
        float act = fmaf(tanh_mufu(gate * s_in), s_in, s_add);

        float tg16 = __shfl_xor_sync(0xFFFFFFFFu, act, 16);
        float fv   = __shfl_xor_sync(0xFFFFFFFFu, act, 8);
        float ov   = __shfl_xor_sync(0xFFFFFFFFu, act, 24);

        if (g == 0) {
            c = fv * c + act * tg16;
            float hv = ov * tanh_mufu(c);
            h_buf[1 - p][j] = hv;
            seqp[0] = hv;
        }
        __syncthreads();
        p ^= 1;
        seqp += BATCH * 64;
        gx_c = gx_n; gx_n = gx_f;
    }
}

// ---------------- K3: QKV GEMM via tf32 mma.sync (R11 proven) ----------------
__global__ void __launch_bounds__(256) k3_qkv(
    const float* __restrict__ Wq, const float* __restrict__ bq,
    const float* __restrict__ Wk, const float* __restrict__ bk,
    const float* __restrict__ Wv, const float* __restrict__ bv)
{
    __shared__ unsigned As[64 * 68];
    __shared__ unsigned Bs[64 * 68];
    int tid = threadIdx.x;
    int mt = blockIdx.x, nt = blockIdx.y;

    const float* W; const float* bias; float* out; int n0;
    if (nt < 3)      { W = Wq; bias = bq; out = d_q; n0 = nt * 64; }
    else if (nt < 6) { W = Wk; bias = bk; out = d_k; n0 = (nt - 3) * 64; }
    else             { W = Wv; bias = bv; out = d_v; n0 = (nt - 6) * 64; }

#pragma unroll
    for (int s = 0; s < 4; s++) {
        int e = tid + s * 256;
        int r = e >> 4, c4 = e & 15;
        float4 v = *(const float4*)&d_seq[(mt * 64 + r) * 64 + c4 * 4];
        uint4 u = make_uint4(cvt_tf32(v.x), cvt_tf32(v.y), cvt_tf32(v.z), cvt_tf32(v.w));
        *(uint4*)&As[r * 68 + c4 * 4] = u;
    }
#pragma unroll
    for (int s = 0; s < 4; s++) {
        int e = tid + s * 256;
        int r = e >> 4, c4 = e & 15;
        float4 v = *(const float4*)&W[(n0 + r) * 64 + c4 * 4];
        uint4 u = make_uint4(cvt_tf32(v.x), cvt_tf32(v.y), cvt_tf32(v.z), cvt_tf32(v.w));
        *(uint4*)&Bs[r * 68 + c4 * 4] = u;
    }
    __syncthreads();

    int lane = tid & 31, wid = tid >> 5;
    int wm = wid >> 1, wn = wid & 1;
    int g = lane >> 2, tg = lane & 3;

    float acc[4][4] = {};
    int ar0 = (wm * 16 + g) * 68;
    int ar1 = ar0 + 8 * 68;
#pragma unroll
    for (int k8 = 0; k8 < 8; k8++) {
        int kb = k8 * 8 + tg;
        unsigned a0 = As[ar0 + kb];
        unsigned a1 = As[ar1 + kb];
        unsigned a2 = As[ar0 + kb + 4];
        unsigned a3 = As[ar1 + kb + 4];
#pragma unroll
        for (int ntl = 0; ntl < 4; ntl++) {
            int bb = (wn * 32 + ntl * 8 + g) * 68 + kb;
            unsigned b0 = Bs[bb];
            unsigned b1 = Bs[bb + 4];
            mma_tf32(acc[ntl][0], acc[ntl][1], acc[ntl][2], acc[ntl][3],
                     a0, a1, a2, a3, b0, b1);
        }
    }

#pragma unroll
    for (int ntl = 0; ntl < 4; ntl++) {
        int col = n0 + wn * 32 + ntl * 8 + 2 * tg;
        float2 b2 = *(const float2*)&bias[col];
        int row0 = mt * 64 + wm * 16 + g;
        float2 o0 = make_float2(acc[ntl][0] + b2.x, acc[ntl][1] + b2.y);
        float2 o1 = make_float2(acc[ntl][2] + b2.x, acc[ntl][3] + b2.y);
        *(float2*)&out[row0 * EMB + col] = o0;
        *(float2*)&out[(row0 + 8) * EMB + col] = o1;
    }
}

// ---------------- K4: attention via tf32 mma.sync (R11 proven) ----------------
__global__ void __launch_bounds__(128) k4_attn()
{
    __shared__ __align__(16) unsigned qt[40 * 52];
    __shared__ __align__(16) unsigned kt[40 * 52];
    __shared__ __align__(16) unsigned vt[40 * 52];
    __shared__ __align__(16) float ss[40 * 44];
    int t = blockIdx.x, h = blockIdx.y;
    int tid = threadIdx.x;

#pragma unroll
    for (int ii = 0; ii < 12; ii++) {
        int e = tid + ii * 128;
        if (e < 1440) {
            int arr = e / 480, idx = e - arr * 480;
            int r = idx / 12, c4 = idx - r * 12;
            const float* src = arr == 0 ? d_q : (arr == 1 ? d_k : d_v);
            unsigned* dst = arr == 0 ? qt : (arr == 1 ? kt : vt);
            float4 v = *(const float4*)&src[(t * BATCH + r) * EMB + h * DH + c4 * 4];
            uint4 u = make_uint4(cvt_tf32(v.x), cvt_tf32(v.y), cvt_tf32(v.z), cvt_tf32(v.w));
            *(uint4*)&dst[r * 52 + c4 * 4] = u;
        }
    }
    __syncthreads();

    int lane = tid & 31, wid = tid >> 5;
    int g = lane >> 2, tg = lane & 3;

    if (wid < 3) {
        int m0 = wid * 16;
        int r0 = min(m0 + g, 39), r1 = min(m0 + g + 8, 39);
        float acc[5][4] = {};
#pragma unroll
        for (int k8 = 0; k8 < 6; k8++) {
            int kb = k8 * 8 + tg;
            unsigned a0 = qt[r0 * 52 + kb];
            unsigned a1 = qt[r1 * 52 + kb];
            unsigned a2 = qt[r0 * 52 + kb + 4];
            unsigned a3 = qt[r1 * 52 + kb + 4];
#pragma unroll
            for (int ntl = 0; ntl < 5; ntl++) {
                unsigned b0 = kt[(ntl * 8 + g) * 52 + kb];
                unsigned b1 = kt[(ntl * 8 + g) * 52 + kb + 4];
                mma_tf32(acc[ntl][0], acc[ntl][1], acc[ntl][2], acc[ntl][3],
                         a0, a1, a2, a3, b0, b1);
            }
        }
        int row0 = m0 + g, row1 = m0 + g + 8;
#pragma unroll
        for (int ntl = 0; ntl < 5; ntl++) {
            int col = ntl * 8 + 2 * tg;
            if (row0 < 40) {
                ss[row0 * 44 + col] = acc[ntl][0] * 0.125f;
                ss[row0 * 44 + col + 1] = acc[ntl][1] * 0.125f;
            }
            if (row1 < 40) {
                ss[row1 * 44 + col] = acc[ntl][2] * 0.125f;
                ss[row1 * 44 + col + 1] = acc[ntl][3] * 0.125f;
            }
        }
    }
    __syncthreads();

    if (tid < 40) {
        float m = -1e30f;
#pragma unroll
        for (int j = 0; j < 40; j++) m = fmaxf(m, ss[tid * 44 + j]);
        float p[40]; float sum = 0.f;
#pragma unroll
        for (int j = 0; j < 40; j++) { p[j] = __expf(ss[tid * 44 + j] - m); sum += p[j]; }
        float inv = 1.f / sum;
        unsigned* pr = (unsigned*)ss + tid * 44;
#pragma unroll
        for (int j = 0; j < 40; j++) pr[j] = cvt_tf32(p[j] * inv);
    }
    __syncthreads();

    const unsigned* pt = (const unsigned*)ss;
    for (int idx = wid; idx < 18; idx += 4) {
        int mtile = idx / 6, ntile = idx - mtile * 6;
        int m0 = mtile * 16, n0 = ntile * 8;
        int r0 = min(m0 + g, 39), r1 = min(m0 + g + 8, 39);
        float acc0 = 0.f, acc1 = 0.f, acc2 = 0.f, acc3 = 0.f;
#pragma unroll
        for (int k8 = 0; k8 < 5; k8++) {
            int kb = k8 * 8 + tg;
            mma_tf32(acc0, acc1, acc2, acc3,
                     pt[r0 * 44 + kb], pt[r1 * 44 + kb],
                     pt[r0 * 44 + kb + 4], pt[r1 * 44 + kb + 4],
                     vt[kb * 52 + n0 + g], vt[(kb + 4) * 52 + n0 + g]);
        }
        int col = n0 + 2 * tg;
        int row0 = m0 + g, row1 = m0 + g + 8;
        if (row0 < 40)
            *(float2*)&d_att[(t * BATCH + row0) * EMB + h * DH + col] = make_float2(acc0, acc1);
        if (row1 < 40)
            *(float2*)&d_att[(t * BATCH + row1) * EMB + h * DH + col] = make_float2(acc2, acc3);
    }
}

// ---------------- K5: tf32 mma GLU GEMM + GLU + residual + LN (R11 proven) ----------------
__global__ void __launch_bounds__(256) k5_glu_ln(
    const float* __restrict__ Wa, const float* __restrict__ ba,
    const float* __restrict__ Wg, const float* __restrict__ bg,
    const float* __restrict__ gamma, const float* __restrict__ beta,
    float* __restrict__ out)
{
    __shared__ __align__(16) float buf[64 * 136];
    unsigned* As = (unsigned*)buf;
    unsigned* Bs = (unsigned*)buf + 64 * 36;
    float* os = buf;
    int tid = threadIdx.x;
    int mt = blockIdx.x;

    int lane = tid & 31, wid = tid >> 5;
    int wm = wid >> 2, wn = wid & 3;
    int g = lane >> 2, tg = lane & 3;

    float acc[2][4][4] = {};

    for (int kc = 0; kc < 6; kc++) {
#pragma unroll
        for (int s = 0; s < 2; s++) {
            int e = tid + s * 256;
            int r = e >> 3, c4 = e & 7;
            float4 v = *(const float4*)&d_att[(mt * 64 + r) * EMB + kc * 32 + c4 * 4];
            uint4 u = make_uint4(cvt_tf32(v.x), cvt_tf32(v.y), cvt_tf32(v.z), cvt_tf32(v.w));
            *(uint4*)&As[r * 36 + c4 * 4] = u;
        }
#pragma unroll
        for (int s = 0; s < 4; s++) {
            int e = tid + s * 256;
            int r = e >> 3, c4 = e & 7;
            const float* Wsrc = (r < 64) ? &Wa[r * EMB] : &Wg[(r - 64) * EMB];
            float4 v = *(const float4*)&Wsrc[kc * 32 + c4 * 4];
            uint4 u = make_uint4(cvt_tf32(v.x), cvt_tf32(v.y), cvt_tf32(v.z), cvt_tf32(v.w));
            *(uint4*)&Bs[r * 36 + c4 * 4] = u;
        }
        __syncthreads();

#pragma unroll
        for (int k8 = 0; k8 < 4; k8++) {
            int kb = k8 * 8 + tg;
            unsigned a[2][4];
#pragma unroll
            for (int mtl = 0; mtl < 2; mtl++) {
                int ar0 = (wm * 32 + mtl * 16 + g) * 36;
                a[mtl][0] = As[ar0 + kb];
                a[mtl][1] = As[ar0 + 8 * 36 + kb];
                a[mtl][2] = As[ar0 + kb + 4];
                a[mtl][3] = As[ar0 + 8 * 36 + kb + 4];
            }
#pragma unroll
            for (int ntl = 0; ntl < 4; ntl++) {
                int bb = (wn * 32 + ntl * 8 + g) * 36 + kb;
                unsigned b0 = Bs[bb];
                unsigned b1 = Bs[bb + 4];
#pragma unroll
                for (int mtl = 0; mtl < 2; mtl++)
                    mma_tf32(acc[mtl][ntl][0], acc[mtl][ntl][1],
                             acc[mtl][ntl][2], acc[mtl][ntl][3],
                             a[mtl][0], a[mtl][1], a[mtl][2], a[mtl][3], b0, b1);
            }
        }
        __syncthreads();
    }

#pragma unroll
    for (int mtl = 0; mtl < 2; mtl++) {
#pragma unroll
        for (int ntl = 0; ntl < 4; ntl++) {
            int col = wn * 32 + ntl * 8 + 2 * tg;
            float2 b2 = (col < 64) ? *(const float2*)&ba[col]
                                   : *(const float2*)&bg[col - 64];
            int row0 = wm * 32 + mtl * 16 + g;
            os[row0 * 136 + col]     = acc[mtl][ntl][0] + b2.x;
            os[row0 * 136 + col + 1] = acc[mtl][ntl][1] + b2.y;
            os[(row0 + 8) * 136 + col]     = acc[mtl][ntl][2] + b2.x;
            os[(row0 + 8) * 136 + col + 1] = acc[mtl][ntl][3] + b2.y;
        }
    }
    __syncthreads();

    {
        int r = tid >> 2, q = tid & 3;
        int c0 = q * 16;
        int grow = mt * 64 + r;
        float y[16];
        float s = 0.f, s2 = 0.f;
#pragma unroll
        for (int c = 0; c < 16; c++) {
            int j = c0 + c;
            float a = os[r * 136 + j];
            float g2 = os[r * 136 + 64 + j];
            float yv = d_seq[grow * 64 + j] + a * sigf(g2);
            y[c] = yv; s += yv; s2 += yv * yv;
        }
        s += __shfl_xor_sync(0xFFFFFFFFu, s, 1);
        s += __shfl_xor_sync(0xFFFFFFFFu, s, 2);
        s2 += __shfl_xor_sync(0xFFFFFFFFu, s2, 1);
        s2 += __shfl_xor_sync(0xFFFFFFFFu, s2, 2);
        float mu = s * (1.f / 64.f);
        float var = s2 * (1.f / 64.f) - mu * mu;
        float inv = rsqrtf(var + 1e-5f);
#pragma unroll
        for (int c = 0; c < 16; c++) {
            int j = c0 + c;
            out[grow * 64 + j] = (y[c] - mu) * inv * gamma[j] + beta[j];
        }
    }
}

// ---------------- launch ----------------
extern "C" void kernel_launch(void* const* d_in, const int* in_sizes, int n_in,
                              void* d_out, int out_size)
{
    const float* hist = (const float*)d_in[0];
    const float* W1   = (const float*)d_in[2];
    const float* b1   = (const float*)d_in[3];
    const float* W_ih = (const float*)d_in[4];
    const float* W_hh = (const float*)d_in[5];
    const float* b_ih = (const float*)d_in[6];
    const float* b_hh = (const float*)d_in[7];
    const float* Wq   = (const float*)d_in[8];
    const float* bq   = (const float*)d_in[9];
    const float* Wk   = (const float*)d_in[10];
    const float* bk   = (const float*)d_in[11];
    const float* Wv   = (const float*)d_in[12];
    const float* bv   = (const float*)d_in[13];
    const float* Wa   = (const float*)d_in[14];
    const float* ba   = (const float*)d_in[15];
    const float* Wg   = (const float*)d_in[16];
    const float* bg   = (const float*)d_in[17];
    const float* gamma= (const float*)d_in[18];
    const float* beta = (const float*)d_in[19];
    float* out = (float*)d_out;

    k1_embed_gates<<<ROWS / 8, 256>>>(hist, W1, b1, W_ih, b_ih, b_hh);
    k2_lstm<<<BATCH, 256>>>(W_hh);
    k3_qkv<<<dim3(ROWS / 64, 9), 256>>>(Wq, bq, Wk, bk, Wv, bv);
    k4_attn<<<dim3(SEQ, NH), 128>>>();
    k5_glu_ln<<<ROWS / 64, 256>>>(Wa, ba, Wg, bg, gamma, beta, out);
}